// round 12
// baseline (speedup 1.0000x reference)
#include <cuda_runtime.h>
#include <cuda_fp16.h>
#include <math.h>
#include <stdint.h>

#define N_ATOMS 50000
#define E_EDGES 1600000
#define H_DIM   128
#define B_GR    64
#define T_OUT   4
#define G_RBF   10
#define HH      (H_DIM*H_DIM)
#define TBL     1024
#define DMAX    10.0f

// -------- scratch (device globals; no allocations allowed) --------
__device__ float  g_h  [N_ATOMS*H_DIM];
__device__ float  g_hx [N_ATOMS*H_DIM];
__device__ __half g_hxh[N_ATOMS*H_DIM];
__device__ float  g_agg[N_ATOMS*H_DIM];
__device__ float  g_h2 [N_ATOMS*64];
__device__ __half g_tblh[2*TBL*H_DIM];
__device__ float  g_pool2[B_GR*64];
__device__ float  g_cnt[B_GR];

__device__ __forceinline__ float sspf(float x) {
    float sp = fmaxf(x, 0.0f) + log1pf(expf(-fabsf(x)));
    return sp - 0.69314718055994530942f;
}

__device__ __forceinline__ uint32_t tf32_of(float x) {
    uint32_t r;
    asm("cvt.rna.tf32.f32 %0, %1;" : "=r"(r) : "f"(x));
    return r;
}

__device__ __forceinline__ void mma_tf32(float* c, uint32_t a0, uint32_t a1,
                                         uint32_t a2, uint32_t a3,
                                         uint32_t b0, uint32_t b1) {
    asm volatile(
        "mma.sync.aligned.m16n8k8.row.col.f32.tf32.tf32.f32 "
        "{%0,%1,%2,%3}, {%4,%5,%6,%7}, {%8,%9}, {%0,%1,%2,%3};"
        : "+f"(c[0]), "+f"(c[1]), "+f"(c[2]), "+f"(c[3])
        : "r"(a0), "r"(a1), "r"(a2), "r"(a3), "r"(b0), "r"(b1));
}

// -------- filter table build (fp32 math, half store) --------
__global__ void build_table(const float* __restrict__ w1, const float* __restrict__ b1,
                            const float* __restrict__ w2, const float* __restrict__ b2)
{
    __shared__ float t1[H_DIM];
    const int k = blockIdx.x, it = blockIdx.y, h = threadIdx.x;
    const float d = (float)k * (DMAX / (float)(TBL - 1));
    const float step  = 10.0f / 9.0f;
    const float coeff = -0.405f;

    float v = b1[it*H_DIM + h];
    const float* w1p = w1 + it*G_RBF*H_DIM;
#pragma unroll
    for (int g = 0; g < G_RBF; g++) {
        float t = d - step * (float)g;
        v = fmaf(expf(coeff * t * t), w1p[g*H_DIM + h], v);
    }
    t1[h] = sspf(v);
    __syncthreads();

    const float* w2p = w2 + it*HH;
    float acc = b2[it*H_DIM + h];
#pragma unroll 8
    for (int kk = 0; kk < H_DIM; kk++)
        acc = fmaf(t1[kk], w2p[kk*H_DIM + h], acc);

    float C = 0.5f * (cospif(d * 0.1f) + 1.0f);
    g_tblh[(it*TBL + k)*H_DIM + h] = __float2half_rn(acc * C);
}

// -------- edge pass: one warp per edge, fp16 loads, fp32 math+red --------
#define EPW 2
__global__ void __launch_bounds__(256)
edge_pass(const int* __restrict__ ei, const float* __restrict__ pos,
          const __half* __restrict__ tbl)
{
    const int gw   = (blockIdx.x * 256 + threadIdx.x) >> 5;
    const int lane = threadIdx.x & 31;
    const int e0 = gw * EPW;
    const float scale = (float)(TBL - 1) / DMAX;

#pragma unroll
    for (int j = 0; j < EPW; j++) {
        int e = e0 + j;
        int s  = __ldg(&ei[e]);
        int dn = __ldg(&ei[E_EDGES + e]);
        float dx = __ldg(&pos[s*3+0]) - __ldg(&pos[dn*3+0]);
        float dy = __ldg(&pos[s*3+1]) - __ldg(&pos[dn*3+1]);
        float dz = __ldg(&pos[s*3+2]) - __ldg(&pos[dn*3+2]);
        float d = sqrtf(dx*dx + dy*dy + dz*dz);

        float tt = d * scale;
        int i0 = (int)tt;
        i0 = min(i0, TBL - 2);
        float f = tt - (float)i0;

        const uint2* ta = reinterpret_cast<const uint2*>(tbl + (size_t)i0 * H_DIM);
        uint2 av = __ldg(&ta[lane]);
        uint2 bv = __ldg(&ta[lane + 32]);
        uint2 xv = __ldg(reinterpret_cast<const uint2*>(g_hxh + (size_t)s * H_DIM) + lane);

        float2 a0 = __half22float2(*reinterpret_cast<__half2*>(&av.x));
        float2 a1 = __half22float2(*reinterpret_cast<__half2*>(&av.y));
        float2 b0 = __half22float2(*reinterpret_cast<__half2*>(&bv.x));
        float2 b1 = __half22float2(*reinterpret_cast<__half2*>(&bv.y));
        float2 x0 = __half22float2(*reinterpret_cast<__half2*>(&xv.x));
        float2 x1 = __half22float2(*reinterpret_cast<__half2*>(&xv.y));

        float w0 = fmaf(f, b0.x - a0.x, a0.x) * x0.x;
        float w1 = fmaf(f, b0.y - a0.y, a0.y) * x0.y;
        float w2 = fmaf(f, b1.x - a1.x, a1.x) * x1.x;
        float w3 = fmaf(f, b1.y - a1.y, a1.y) * x1.y;

        float* ap = g_agg + (size_t)dn*H_DIM + lane*4;
        asm volatile("red.global.add.v4.f32 [%0], {%1,%2,%3,%4};"
                     :: "l"(ap), "f"(w0), "f"(w1), "f"(w2), "f"(w3) : "memory");
    }
}

// -------- tensor-core node GEMM (tf32 HMMA), v2 --------
// Block: 256 thr = 8 warps arranged 4 row-groups x 2 col-groups.
// Block computes 64 rows x NN cols; each warp 16 rows x NN/2 cols (acc=32 regs).
// W staged tf32 in smem (pad 8 -> conflict-free); A prefetched 1 k-step ahead.
template<int NN, bool SSP_, bool RESID, bool OUTH>
__global__ void __launch_bounds__(256, 3)
node_gemm_tc(const float* __restrict__ A, const int* __restrict__ gidxA,
             const float* __restrict__ W, const float* __restrict__ bias,
             const float* __restrict__ resid, const int* __restrict__ gidxR,
             void* __restrict__ CoutV, int M)
{
    constexpr int S  = NN + 8;
    constexpr int NC = NN / 2;      // cols per warp
    constexpr int NT = NC / 8;      // n8 tiles per warp
    extern __shared__ float sW[];   // [128][S]

    const int tid = threadIdx.x;
    for (int idx = tid; idx < 128*NN; idx += 256) {
        int k = idx / NN, n = idx - k*NN;
        sW[k*S + n] = __uint_as_float(tf32_of(W[idx]));
    }
    __syncthreads();

    const int warp = tid >> 5, lane = tid & 31;
    const int wr = warp >> 1, wc = warp & 1;
    const int row0 = blockIdx.x * 64 + wr * 16;
    const int g  = lane >> 2;
    const int qc = lane & 3;
    int rA0 = min(row0 + g,     M - 1);
    int rA1 = min(row0 + 8 + g, M - 1);
    if (gidxA) { rA0 = gidxA[rA0]; rA1 = gidxA[rA1]; }
    const float* A0 = A + (size_t)rA0 * 128 + qc;
    const float* A1 = A + (size_t)rA1 * 128 + qc;

    float acc[NT][4];
#pragma unroll
    for (int t = 0; t < NT; t++)
#pragma unroll
        for (int i = 0; i < 4; i++) acc[t][i] = 0.0f;

    uint32_t a0 = tf32_of(__ldg(A0));
    uint32_t a2 = tf32_of(__ldg(A0 + 4));
    uint32_t a1 = tf32_of(__ldg(A1));
    uint32_t a3 = tf32_of(__ldg(A1 + 4));

#pragma unroll
    for (int k0 = 0; k0 < 128; k0 += 8) {
        uint32_t n0 = a0, n1 = a1, n2 = a2, n3 = a3;
        if (k0 < 120) {
            n0 = tf32_of(__ldg(A0 + k0 + 8));
            n2 = tf32_of(__ldg(A0 + k0 + 12));
            n1 = tf32_of(__ldg(A1 + k0 + 8));
            n3 = tf32_of(__ldg(A1 + k0 + 12));
        }
        const float* bp0 = sW + (k0 + qc) * S + wc*NC + g;
        const float* bp1 = bp0 + 4 * S;
#pragma unroll
        for (int t = 0; t < NT; t++) {
            uint32_t b0 = __float_as_uint(bp0[t*8]);
            uint32_t b1 = __float_as_uint(bp1[t*8]);
            mma_tf32(acc[t], a0, a1, a2, a3, b0, b1);
        }
        a0 = n0; a1 = n1; a2 = n2; a3 = n3;
    }

    const int r0 = row0 + g;
    const int r1 = r0 + 8;
    int rR0 = 0, rR1 = 0;
    if (RESID) {
        rR0 = min(r0, M - 1); rR1 = min(r1, M - 1);
        if (gidxR) { rR0 = gidxR[rR0]; rR1 = gidxR[rR1]; }
    }
#pragma unroll
    for (int t = 0; t < NT; t++) {
        int nc = wc*NC + t*8 + 2*qc;
        float bias0 = 0.f, bias1 = 0.f;
        if (bias) { bias0 = bias[nc]; bias1 = bias[nc+1]; }
        if (r0 < M) {
            float v0 = acc[t][0] + bias0;
            float v1 = acc[t][1] + bias1;
            if (SSP_) { v0 = sspf(v0); v1 = sspf(v1); }
            if (RESID) { v0 += resid[(size_t)rR0*NN + nc]; v1 += resid[(size_t)rR0*NN + nc + 1]; }
            if (OUTH) {
                *reinterpret_cast<__half2*>((__half*)CoutV + (size_t)r0*NN + nc) =
                    __floats2half2_rn(v0, v1);
            } else {
                float* Cout = (float*)CoutV;
                Cout[(size_t)r0*NN + nc]     = v0;
                Cout[(size_t)r0*NN + nc + 1] = v1;
            }
        }
        if (r1 < M) {
            float v2 = acc[t][2] + bias0;
            float v3 = acc[t][3] + bias1;
            if (SSP_) { v2 = sspf(v2); v3 = sspf(v3); }
            if (RESID) { v2 += resid[(size_t)rR1*NN + nc]; v3 += resid[(size_t)rR1*NN + nc + 1]; }
            if (OUTH) {
                *reinterpret_cast<__half2*>((__half*)CoutV + (size_t)r1*NN + nc) =
                    __floats2half2_rn(v2, v3);
            } else {
                float* Cout = (float*)CoutV;
                Cout[(size_t)r1*NN + nc]     = v2;
                Cout[(size_t)r1*NN + nc + 1] = v3;
            }
        }
    }
}

// -------- readout: pool h2 [N,64] per graph + atom counts --------
__global__ void pool2_kernel(const int* __restrict__ batch) {
    int idx = blockIdx.x * 256 + threadIdx.x;
    if (idx < N_ATOMS*64) {
        int n = idx >> 6, c = idx & 63;
        int b = batch[n];
        atomicAdd(&g_pool2[b*64 + c], g_h2[idx]);
        if (c == 0) atomicAdd(&g_cnt[b], 1.0f);
    }
}

// -------- final --------
__global__ void final_kernel(const float* __restrict__ out2w, const float* __restrict__ out2b,
                             const float* __restrict__ predw, const float* __restrict__ predb,
                             float* __restrict__ out)
{
    __shared__ float M[64*T_OUT];
    __shared__ float obp[T_OUT];
    int t = threadIdx.x;
    {
        int c = t >> 2, j = t & 3;
        float acc = 0.0f;
        for (int h = 0; h < H_DIM; h++)
            acc = fmaf(out2w[c*H_DIM + h], predw[h*T_OUT + j], acc);
        M[c*T_OUT + j] = acc;
    }
    if (t < T_OUT) {
        float acc = 0.0f;
        for (int h = 0; h < H_DIM; h++)
            acc = fmaf(out2b[h], predw[h*T_OUT + t], acc);
        obp[t] = acc;
    }
    __syncthreads();
    int b = t >> 2, j = t & 3;
    float acc = predb[j] + g_cnt[b] * obp[j];
    for (int c = 0; c < 64; c++)
        acc = fmaf(g_pool2[b*64 + c], M[c*T_OUT + j], acc);
    out[b*T_OUT + j] = acc;
}

extern "C" void kernel_launch(void* const* d_in, const int* in_sizes, int n_in,
                              void* d_out, int out_size)
{
    const int*   z      = (const int*)  d_in[0];
    const float* pos    = (const float*)d_in[1];
    const int*   batch  = (const int*)  d_in[2];
    const int*   ei     = (const int*)  d_in[3];
    const float* emb    = (const float*)d_in[4];
    const float* mlp_w1 = (const float*)d_in[5];
    const float* mlp_b1 = (const float*)d_in[6];
    const float* mlp_w2 = (const float*)d_in[7];
    const float* mlp_b2 = (const float*)d_in[8];
    const float* lin1_w = (const float*)d_in[9];
    const float* lin2_w = (const float*)d_in[10];
    const float* lin2_b = (const float*)d_in[11];
    const float* lin_w  = (const float*)d_in[12];
    const float* lin_b  = (const float*)d_in[13];
    const float* out1_w = (const float*)d_in[14];
    const float* out1_b = (const float*)d_in[15];
    const float* out2_w = (const float*)d_in[16];
    const float* out2_b = (const float*)d_in[17];
    const float* pred_w = (const float*)d_in[18];
    const float* pred_b = (const float*)d_in[19];
    float* out = (float*)d_out;

    void *h_p, *hx_p, *hxh_p, *agg_p, *h2_p, *tbl_p, *pool_p, *cnt_p;
    cudaGetSymbolAddress(&h_p,    g_h);
    cudaGetSymbolAddress(&hx_p,   g_hx);
    cudaGetSymbolAddress(&hxh_p,  g_hxh);
    cudaGetSymbolAddress(&agg_p,  g_agg);
    cudaGetSymbolAddress(&h2_p,   g_h2);
    cudaGetSymbolAddress(&tbl_p,  g_tblh);
    cudaGetSymbolAddress(&pool_p, g_pool2);
    cudaGetSymbolAddress(&cnt_p,  g_cnt);
    float*  hF   = (float*)h_p;
    float*  hxF  = (float*)hx_p;
    float*  aggF = (float*)agg_p;
    float*  h2F  = (float*)h2_p;
    __half* tblH = (__half*)tbl_p;

    const int smem128 = 128 * (128 + 8) * 4;   // 69632 -> 3 blocks/SM
    const int smem64  = 128 * (64 + 8) * 4;    // 36864
    cudaFuncSetAttribute(node_gemm_tc<128,false,false,true >, cudaFuncAttributeMaxDynamicSharedMemorySize, smem128);
    cudaFuncSetAttribute(node_gemm_tc<128,true ,false,false>, cudaFuncAttributeMaxDynamicSharedMemorySize, smem128);
    cudaFuncSetAttribute(node_gemm_tc<128,false,true ,false>, cudaFuncAttributeMaxDynamicSharedMemorySize, smem128);
    cudaFuncSetAttribute(node_gemm_tc<64 ,true ,false,false>, cudaFuncAttributeMaxDynamicSharedMemorySize, smem64);

    build_table<<<dim3(TBL, 2), H_DIM>>>(mlp_w1, mlp_b1, mlp_w2, mlp_b2);

    const int NBG = (N_ATOMS + 63) / 64;   // 782 (64 rows per block)
    const int EB  = E_EDGES / (EPW * 8);   // 100000 blocks
    for (int i = 0; i < 2; i++) {
        if (i == 0)
            node_gemm_tc<128,false,false,true ><<<NBG,256,smem128>>>(emb, z, lin1_w, nullptr, nullptr, nullptr, hxh_p, N_ATOMS);
        else
            node_gemm_tc<128,false,false,true ><<<NBG,256,smem128>>>(hF, nullptr, lin1_w + HH, nullptr, nullptr, nullptr, hxh_p, N_ATOMS);
        cudaMemsetAsync(agg_p, 0, (size_t)N_ATOMS*H_DIM*sizeof(float));
        edge_pass<<<EB, 256>>>(ei, pos, tblH + i*TBL*H_DIM);
        node_gemm_tc<128,true ,false,false><<<NBG,256,smem128>>>(aggF, nullptr, lin2_w + i*HH, lin2_b + i*H_DIM, nullptr, nullptr, hxF, N_ATOMS);
        if (i == 0)
            node_gemm_tc<128,false,true ,false><<<NBG,256,smem128>>>(hxF, nullptr, lin_w, lin_b, emb, z, hF, N_ATOMS);
        else
            node_gemm_tc<128,false,true ,false><<<NBG,256,smem128>>>(hxF, nullptr, lin_w + HH, lin_b + H_DIM, hF, nullptr, hF, N_ATOMS);
    }

    node_gemm_tc<64,true,false,false><<<NBG,256,smem64>>>(hF, nullptr, out1_w, out1_b, nullptr, nullptr, h2F, N_ATOMS);

    cudaMemsetAsync(pool_p, 0, (size_t)B_GR*64*sizeof(float));
    cudaMemsetAsync(cnt_p,  0, (size_t)B_GR*sizeof(float));
    pool2_kernel<<<(N_ATOMS*64 + 255)/256, 256>>>(batch);
    final_kernel<<<1, 256>>>(out2_w, out2_b, pred_w, pred_b, out);
}